// round 15
// baseline (speedup 1.0000x reference)
#include <cuda_runtime.h>
#include <cuda_fp16.h>

#define NN 50000
#define FF 16
#define EE 800000
#define HH 64
#define TOUT 10
#define NF (NN*FF)

#define STHR 512
#define BWARP 16                 // warps per block
#define NPBLK (BWARP*2)          // 32 nodes per block
#define SBLK ((NN + NPBLK - 1)/NPBLK)   // 1563

// ---------------- device state ----------------
__device__ float   g_x0[NF];
__device__ float   g_xi[NF];
__device__ float   g_k[6][NF];
__device__ __half2 g_uv[2][NN*32];   // packed u: (.x=ch lane, .y=ch lane+32), double-buffered
__device__ float   g_v[NN*HH];
__device__ float   g_augproj[NN*HH];
__device__ float   g_ys[TOUT*NF];
__device__ int     g_deg[NN];
__device__ int     g_rowptr[NN+1];
__device__ int     g_wptr[NN];
__device__ int     g_src_sorted[EE];
__device__ float4  g_ea_sorted[EE];

// DOPRI5 coefficients. Row 0 unused, rows 1..5 = A[0..4], row 6 = B.
__constant__ float c_coef[7][6] = {
  {0.f,0.f,0.f,0.f,0.f,0.f},
  {(float)(0.2), 0.f,0.f,0.f,0.f,0.f},
  {(float)(3.0/40.0), (float)(9.0/40.0), 0.f,0.f,0.f,0.f},
  {(float)(44.0/45.0), (float)(-56.0/15.0), (float)(32.0/9.0), 0.f,0.f,0.f},
  {(float)(19372.0/6561.0), (float)(-25360.0/2187.0), (float)(64448.0/6561.0), (float)(-212.0/729.0), 0.f,0.f},
  {(float)(9017.0/3168.0), (float)(-355.0/33.0), (float)(46732.0/5247.0), (float)(49.0/176.0), (float)(-5103.0/18656.0), 0.f},
  {(float)(35.0/384.0), 0.f, (float)(500.0/1113.0), (float)(125.0/192.0), (float)(-2187.0/6784.0), (float)(11.0/84.0)}
};
__constant__ float c_C[6] = {0.f, 0.2f, 0.3f, 0.8f, (float)(8.0/9.0), 1.f};

__device__ __forceinline__ float tanha(float x) {
  float r;
  asm("tanh.approx.f32 %0, %1;" : "=f"(r) : "f"(x));
  return r;
}

// ---------------- launch 1: combo = state init + augproj + u/v projection + deg zero ----------------
__global__ __launch_bounds__(256) void combo_kernel(
    const float* __restrict__ xh, const float* __restrict__ xm,
    const float* __restrict__ W1m, const float* __restrict__ b1m,
    const float* __restrict__ W1n, const float* __restrict__ b1n)
{
  __shared__ float saug[4][176];
  __shared__ float sW[32 * 64];
  __shared__ float sxi[4][16];
  __shared__ float sb[64];
  int b = blockIdx.x;
  int tid = threadIdx.x;
  int gid = b * 256 + tid;
  if (gid < NN) g_deg[gid] = 0;
  int ln = tid >> 6;
  int ch = tid & 63;
  int n = b * 4 + ln;
  #pragma unroll
  for (int i = tid; i < 512; i += 256) ((float4*)sW)[i] = ((const float4*)W1m)[i];
  if (tid < 16) ((float4*)sb)[tid] = ((const float4*)b1m)[tid];
  if (ch < 16) {
    int f = ch;
    float xs[10], ms[10];
    float sm = 0.f, cm = 0.f;
    #pragma unroll
    for (int tt = 0; tt < 10; tt++) {
      xs[tt] = xh[(tt * NN + n) * FF + f];
      ms[tt] = xm[tt * NN + n];
      sm += xs[tt] * ms[tt];
      cm += ms[tt];
    }
    float cnt = fmaxf(cm, 1.0f);
    float mean = sm / cnt;
    float var = 0.f;
    #pragma unroll
    for (int tt = 0; tt < 10; tt++) { float d = xs[tt] - mean; var += d * d * ms[tt]; }
    var /= cnt;
    #pragma unroll
    for (int tt = 0; tt < 9; tt++)
      saug[ln][tt * 16 + f] = (xs[tt + 1] - xs[tt]) * (ms[tt + 1] * ms[tt]);
    saug[ln][144 + f] = mean;
    saug[ln][160 + f] = var;
    int idx = n * 16 + f;
    float xv = xs[9];
    g_x0[idx] = xv;
    g_xi[idx] = xv;
    sxi[ln][f] = xv;
  }
  __syncthreads();
  {
    float acc = b1n[ch];
    #pragma unroll 8
    for (int r = 0; r < 176; r++)
      acc += saug[ln][r] * W1n[(32 + r) * 64 + ch];
    g_augproj[n * 64 + ch] = acc;
  }
  if (ch < 32) {
    int lane = ch;
    float u0 = 0.f, u1 = 0.f;
    float v0 = sb[lane], v1 = sb[32 + lane];
    #pragma unroll
    for (int i = 0; i < 16; i++) {
      float xv = sxi[ln][i];
      u0 += xv * sW[i * 64 + lane];
      u1 += xv * sW[i * 64 + 32 + lane];
      v0 += xv * sW[(16 + i) * 64 + lane];
      v1 += xv * sW[(16 + i) * 64 + 32 + lane];
    }
    g_uv[0][n * 32 + lane] = __floats2half2_rn(u0, u1);
    g_v[n * 64 + lane] = v0;
    g_v[n * 64 + 32 + lane] = v1;
  }
}

// ---------------- launch 2: single-block histogram + rowptr scan ----------------
__global__ __launch_bounds__(1024) void histscan_kernel(const int* __restrict__ ei) {
  __shared__ int wsum[32];
  int tid = threadIdx.x, lane = tid & 31, wid = tid >> 5;
  for (int e = tid; e < EE; e += 1024)
    atomicAdd(&g_deg[ei[EE + e]], 1);
  __syncthreads();
  int carry = 0;
  for (int base = 0; base < NN; base += 1024) {
    int i = base + tid;
    int v = (i < NN) ? g_deg[i] : 0;
    int x = v;
    #pragma unroll
    for (int o = 1; o < 32; o <<= 1) { int y = __shfl_up_sync(0xffffffffu, x, o); if (lane >= o) x += y; }
    if (lane == 31) wsum[wid] = x;
    __syncthreads();
    if (wid == 0) {
      int s = wsum[lane];
      #pragma unroll
      for (int o = 1; o < 32; o <<= 1) { int y = __shfl_up_sync(0xffffffffu, s, o); if (lane >= o) s += y; }
      wsum[lane] = s;
    }
    __syncthreads();
    int incl = x + carry + (wid > 0 ? wsum[wid - 1] : 0);
    if (i < NN) { g_rowptr[i + 1] = incl; g_wptr[i] = incl - v; }
    carry += wsum[31];
    __syncthreads();
  }
  if (tid == 0) g_rowptr[0] = 0;
}

// ---------------- launch 3: edge scatter into CSR ----------------
__global__ __launch_bounds__(256) void scatter_kernel(
    const int* __restrict__ ei, const float* __restrict__ ea)
{
  int e = blockIdx.x * 256 + threadIdx.x;
  if (e < EE) {
    int d = ei[EE + e];
    int pos = atomicAdd(&g_wptr[d], 1);
    g_src_sorted[pos] = ei[e];
    g_ea_sorted[pos] = ((const float4*)ea)[e];
  }
}

// ---------------- launch 4..243: fused per-stage kernel, 2 nodes/warp, 16 warps/block ----------------
__global__ __launch_bounds__(STHR) void edge_node_kernel(
    int s, int it, int sub, int outrow, int pbuf,
    const float* __restrict__ t,
    const float* __restrict__ W1m, const float* __restrict__ W2m,
    const float* __restrict__ b2m, const float* __restrict__ W1n,
    const float* __restrict__ W2n, const float* __restrict__ b2n,
    const float* __restrict__ b1m)
{
  __shared__ float sWea[4 * 64];
  __shared__ float sW2m[64 * 16];
  __shared__ float sW1nx[16 * 64];
  __shared__ float sW1na[16 * 64];
  __shared__ float sW2n[64 * 16];
  __shared__ float sW1m[32 * 64];
  __shared__ float swt[64];
  __shared__ float sb1m[64];
  __shared__ float sb2m[16], sb2n[16];
  __shared__ float sbuf[BWARP][128];   // 2 nodes x 64 ch per warp
  __shared__ float sxi[BWARP][32];     // 2 nodes x 16
  __shared__ float sagg[BWARP][32];
  __shared__ float sxin[BWARP][32];

  int tid = threadIdx.x;
  if (tid < 64)  ((float4*)sWea)[tid] = ((const float4*)(W1m + 32 * 64))[tid];
  if (tid >= 64 && tid < 320)  ((float4*)sW2m)[tid - 64]  = ((const float4*)W2m)[tid - 64];
  if (tid >= 320 && tid < 576 - 64) {
    // covered below by strided loops for clarity
  }
  for (int i = tid; i < 256; i += STHR) {
    ((float4*)sW1nx)[i] = ((const float4*)W1n)[i];
    ((float4*)sW1na)[i] = ((const float4*)(W1n + 1024))[i];
    ((float4*)sW2n)[i]  = ((const float4*)W2n)[i];
  }
  ((float4*)sW1m)[tid] = ((const float4*)W1m)[tid];   // exactly 512 float4
  if (tid < 16) ((float4*)swt)[tid]  = ((const float4*)(W1n + 208 * 64))[tid];
  if (tid >= 16 && tid < 32) ((float4*)sb1m)[tid - 16] = ((const float4*)b1m)[tid - 16];
  if (tid >= 32 && tid < 36) ((float4*)sb2m)[tid - 32] = ((const float4*)b2m)[tid - 32];
  if (tid >= 36 && tid < 40) ((float4*)sb2n)[tid - 36] = ((const float4*)b2n)[tid - 36];

  int w = tid >> 5, lane = tid & 31;
  int n0 = (blockIdx.x * BWARP + w) * 2;   // warp owns nodes n0, n0+1 (contiguous)
  int n1 = n0 + 1;
  if (n0 < NN) sxi[w][lane] = g_xi[n0 * 16 + lane];   // 32 floats = both nodes' xi
  __syncthreads();
  if (n0 >= NN) return;    // warp-uniform; no block syncs after this point

  float tA = t[it], tB = t[it + 1];
  float dti = (tB - tA) * 0.25f;
  float ti = tA + (float)sub * dti + c_C[s] * dti;

  const __half2* __restrict__ U = &g_uv[pbuf][0];
  float v0a = g_v[n0 * 64 + lane], v1a = g_v[n0 * 64 + 32 + lane];
  float v0b = g_v[n1 * 64 + lane], v1b = g_v[n1 * 64 + 32 + lane];
  float wx0 = sWea[lane],        wx1 = sWea[32 + lane];
  float wy0 = sWea[64 + lane],   wy1 = sWea[96 + lane];
  float wz0 = sWea[128 + lane],  wz1 = sWea[160 + lane];
  float ww0 = sWea[192 + lane],  ww1 = sWea[224 + lane];

  int bega = g_rowptr[n0];
  int begb = g_rowptr[n0 + 1];
  int endb = g_rowptr[n0 + 2];
  int da = begb - bega, db = endb - begb;

  float acc0a = 0.f, acc1a = 0.f, acc0b = 0.f, acc1b = 0.f;

  // ---- edge loop node0 (2-deep pipeline, R12-proven) ----
  {
    int e = bega, end = begb;
    float4 eac = make_float4(0.f, 0.f, 0.f, 0.f); __half2 uhc = __float2half2_rn(0.f);
    if (e < end) {
      int srcc = g_src_sorted[e];
      eac = g_ea_sorted[e];
      uhc = U[srcc * 32 + lane];
    }
    for (; e < end; e++) {
      int e1 = e + 1;
      float4 ean = eac; __half2 uhn = uhc;
      if (e1 < end) {
        int srcn = g_src_sorted[e1];
        ean = g_ea_sorted[e1];
        uhn = U[srcn * 32 + lane];
      }
      float2 uf = __half22float2(uhc);
      float a0 = uf.x + v0a;
      float a1 = uf.y + v1a;
      a0 += eac.x * wx0 + eac.y * wy0 + eac.z * wz0 + eac.w * ww0;
      a1 += eac.x * wx1 + eac.y * wy1 + eac.z * wz1 + eac.w * ww1;
      acc0a += tanha(a0);
      acc1a += tanha(a1);
      eac = ean; uhc = uhn;
    }
  }
  // ---- edge loop node1 ----
  {
    int e = begb, end = endb;
    float4 eac = make_float4(0.f, 0.f, 0.f, 0.f); __half2 uhc = __float2half2_rn(0.f);
    if (e < end) {
      int srcc = g_src_sorted[e];
      eac = g_ea_sorted[e];
      uhc = U[srcc * 32 + lane];
    }
    for (; e < end; e++) {
      int e1 = e + 1;
      float4 ean = eac; __half2 uhn = uhc;
      if (e1 < end) {
        int srcn = g_src_sorted[e1];
        ean = g_ea_sorted[e1];
        uhn = U[srcn * 32 + lane];
      }
      float2 uf = __half22float2(uhc);
      float a0 = uf.x + v0b;
      float a1 = uf.y + v1b;
      a0 += eac.x * wx0 + eac.y * wy0 + eac.z * wz0 + eac.w * ww0;
      a1 += eac.x * wx1 + eac.y * wy1 + eac.z * wz1 + eac.w * ww1;
      acc0b += tanha(a0);
      acc1b += tanha(a1);
      eac = ean; uhc = uhn;
    }
  }

  // ---- agg for both nodes: shared W2m reads, float4 h-vector broadcasts ----
  sbuf[w][lane]      = acc0a;
  sbuf[w][32 + lane] = acc1a;
  sbuf[w][64 + lane] = acc0b;
  sbuf[w][96 + lane] = acc1b;
  __syncwarp();
  int j = lane & 15;
  int cbase = (lane < 16) ? 0 : 32;
  float pa = 0.f, pb = 0.f;
  #pragma unroll
  for (int c4 = 0; c4 < 8; c4++) {
    float4 ha = ((const float4*)(sbuf[w] + cbase))[c4];
    float4 hb = ((const float4*)(sbuf[w] + 64 + cbase))[c4];
    float w0 = sW2m[(cbase + c4 * 4 + 0) * 16 + j];
    float w1 = sW2m[(cbase + c4 * 4 + 1) * 16 + j];
    float w2 = sW2m[(cbase + c4 * 4 + 2) * 16 + j];
    float w3 = sW2m[(cbase + c4 * 4 + 3) * 16 + j];
    pa += ha.x * w0 + ha.y * w1 + ha.z * w2 + ha.w * w3;
    pb += hb.x * w0 + hb.y * w1 + hb.z * w2 + hb.w * w3;
  }
  pa += __shfl_xor_sync(0xffffffffu, pa, 16);
  pb += __shfl_xor_sync(0xffffffffu, pb, 16);
  {
    int r = lane >> 4;
    float deg = (float)(r ? db : da);
    float pv = r ? pb : pa;
    sagg[w][lane] = pv + deg * sb2m[j];   // lane = r*16+j
  }
  __syncwarp();

  // ---- hidden layer for both nodes, shared weight reads ----
  float h0a = g_augproj[n0 * 64 + lane]      + ti * swt[lane];
  float h1a = g_augproj[n0 * 64 + 32 + lane] + ti * swt[32 + lane];
  float h0b = g_augproj[n1 * 64 + lane]      + ti * swt[lane];
  float h1b = g_augproj[n1 * 64 + 32 + lane] + ti * swt[32 + lane];
  #pragma unroll
  for (int i = 0; i < 16; i++) {
    float wxa = sW1nx[i * 64 + lane], wxb = sW1nx[i * 64 + 32 + lane];
    float waa = sW1na[i * 64 + lane], wab = sW1na[i * 64 + 32 + lane];
    float xva = sxi[w][i],  xvb = sxi[w][16 + i];
    float ava = sagg[w][i], avb = sagg[w][16 + i];
    h0a += xva * wxa + ava * waa;
    h1a += xva * wxb + ava * wab;
    h0b += xvb * wxa + avb * waa;
    h1b += xvb * wxb + avb * wab;
  }
  __syncwarp();
  sbuf[w][lane]      = tanha(h0a);
  sbuf[w][32 + lane] = tanha(h1a);
  sbuf[w][64 + lane] = tanha(h0b);
  sbuf[w][96 + lane] = tanha(h1b);
  __syncwarp();

  // ---- output layer for both nodes ----
  float oa = 0.f, ob = 0.f;
  #pragma unroll
  for (int c4 = 0; c4 < 8; c4++) {
    float4 ha = ((const float4*)(sbuf[w] + cbase))[c4];
    float4 hb = ((const float4*)(sbuf[w] + 64 + cbase))[c4];
    float w0 = sW2n[(cbase + c4 * 4 + 0) * 16 + j];
    float w1 = sW2n[(cbase + c4 * 4 + 1) * 16 + j];
    float w2 = sW2n[(cbase + c4 * 4 + 2) * 16 + j];
    float w3 = sW2n[(cbase + c4 * 4 + 3) * 16 + j];
    oa += ha.x * w0 + ha.y * w1 + ha.z * w2 + ha.w * w3;
    ob += hb.x * w0 + hb.y * w1 + hb.z * w2 + hb.w * w3;
  }
  oa += __shfl_xor_sync(0xffffffffu, oa, 16);
  ob += __shfl_xor_sync(0xffffffffu, ob, 16);

  // ---- epilogue: all 32 lanes active; lane = r*16 + j handles (node n0+r, col j) ----
  {
    int r = lane >> 4;
    int idx = (n0 + r) * 16 + j;            // lanes cover 32 contiguous floats
    float kval = (r ? ob : oa) + sb2n[j];
    g_k[s][idx] = kval;
    int row = (s < 5) ? s + 1 : 6;
    float acc = c_coef[row][s] * kval;
    #pragma unroll
    for (int jj = 0; jj < 5; jj++) {
      if (jj < s) acc += c_coef[row][jj] * g_k[jj][idx];
    }
    float xv = g_x0[idx] + dti * acc;
    if (s == 5) {
      g_x0[idx] = xv;
      if (outrow >= 0) g_ys[outrow * NF + idx] = xv;
    }
    g_xi[idx] = xv;
    sxin[w][lane] = xv;                      // lane = r*16+j
  }
  __syncwarp();

  // ---- u/v projection for both nodes, shared weight reads ----
  float u0a = 0.f, u1a = 0.f, u0b = 0.f, u1b = 0.f;
  float nv0a = sb1m[lane], nv1a = sb1m[32 + lane];
  float nv0b = nv0a, nv1b = nv1a;
  #pragma unroll
  for (int i = 0; i < 16; i++) {
    float wu0 = sW1m[i * 64 + lane],        wu1 = sW1m[i * 64 + 32 + lane];
    float wv0 = sW1m[(16 + i) * 64 + lane], wv1 = sW1m[(16 + i) * 64 + 32 + lane];
    float xa = sxin[w][i], xb = sxin[w][16 + i];
    u0a  += xa * wu0;  u1a  += xa * wu1;
    nv0a += xa * wv0;  nv1a += xa * wv1;
    u0b  += xb * wu0;  u1b  += xb * wu1;
    nv0b += xb * wv0;  nv1b += xb * wv1;
  }
  g_uv[pbuf ^ 1][n0 * 32 + lane] = __floats2half2_rn(u0a, u1a);
  g_uv[pbuf ^ 1][n1 * 32 + lane] = __floats2half2_rn(u0b, u1b);
  g_v[n0 * 64 + lane] = nv0a;
  g_v[n0 * 64 + 32 + lane] = nv1a;
  g_v[n1 * 64 + lane] = nv0b;
  g_v[n1 * 64 + 32 + lane] = nv1b;
}

__global__ __launch_bounds__(256) void gather_out_kernel(
    const int* __restrict__ mask_idx, float* __restrict__ out)
{
  int idx = blockIdx.x * 256 + threadIdx.x;
  if (idx < TOUT * NF) {
    int row = idx / NF;
    int rem = idx - row * NF;
    out[idx] = g_ys[mask_idx[row] * NF + rem];
  }
}

// ---------------- launcher ----------------
extern "C" void kernel_launch(void* const* d_in, const int* in_sizes, int n_in,
                              void* d_out, int out_size)
{
  const float* x_hist   = (const float*)d_in[0];
  const float* x_mask   = (const float*)d_in[1];
  const int*   ei       = (const int*)d_in[2];
  const float* ea       = (const float*)d_in[3];
  const float* t        = (const float*)d_in[4];
  const int*   mask_idx = (const int*)d_in[5];
  const float* W1m = (const float*)d_in[6];
  const float* b1m = (const float*)d_in[7];
  const float* W2m = (const float*)d_in[8];
  const float* b2m = (const float*)d_in[9];
  const float* W1n = (const float*)d_in[10];
  const float* b1n = (const float*)d_in[11];
  const float* W2n = (const float*)d_in[12];
  const float* b2n = (const float*)d_in[13];
  float* out = (float*)d_out;

  // exactly 3 setup launches -> the 4th process launch is edge_node_kernel (ncu target)
  combo_kernel<<<NN / 4, 256>>>(x_hist, x_mask, W1m, b1m, W1n, b1n);   // 1
  histscan_kernel<<<1, 1024>>>(ei);                                     // 2
  scatter_kernel<<<(EE + 255) / 256, 256>>>(ei, ea);                    // 3

  int L = 0;
  for (int it = 0; it < TOUT; it++) {
    for (int sub = 0; sub < 4; sub++) {
      for (int s = 0; s < 6; s++) {
        int outrow = (s == 5 && sub == 3) ? it : -1;
        edge_node_kernel<<<SBLK, STHR>>>(s, it, sub, outrow, L & 1,
                                         t, W1m, W2m, b2m, W1n, W2n, b2n, b1m);
        L++;
      }
    }
  }

  gather_out_kernel<<<(TOUT * NF + 255) / 256, 256>>>(mask_idx, out);
}

// round 16
// speedup vs baseline: 1.0531x; 1.0531x over previous
#include <cuda_runtime.h>
#include <cuda_fp16.h>

#define NN 50000
#define FF 16
#define EE 800000
#define HH 64
#define TOUT 10
#define NF (NN*FF)

// ---------------- device state ----------------
__device__ float   g_x0[NF];
__device__ float   g_xi[NF];
__device__ float   g_k[6][NF];
__device__ __half2 g_uv[2][NN*32];   // packed u: (.x=ch lane, .y=ch lane+32), double-buffered
__device__ __half2 g_vv[NN*32];      // packed v
__device__ float   g_augproj[NN*HH];
__device__ float   g_ys[TOUT*NF];
__device__ int     g_deg[NN];
__device__ int     g_rowptr[NN+1];
__device__ int     g_wptr[NN];
__device__ int     g_src_sorted[EE];
__device__ uint4   g_ea2[EE];        // ea pre-packed: 4 splat-half2 per edge

// DOPRI5 coefficients. Row 0 unused, rows 1..5 = A[0..4], row 6 = B.
__constant__ float c_coef[7][6] = {
  {0.f,0.f,0.f,0.f,0.f,0.f},
  {(float)(0.2), 0.f,0.f,0.f,0.f,0.f},
  {(float)(3.0/40.0), (float)(9.0/40.0), 0.f,0.f,0.f,0.f},
  {(float)(44.0/45.0), (float)(-56.0/15.0), (float)(32.0/9.0), 0.f,0.f,0.f},
  {(float)(19372.0/6561.0), (float)(-25360.0/2187.0), (float)(64448.0/6561.0), (float)(-212.0/729.0), 0.f,0.f},
  {(float)(9017.0/3168.0), (float)(-355.0/33.0), (float)(46732.0/5247.0), (float)(49.0/176.0), (float)(-5103.0/18656.0), 0.f},
  {(float)(35.0/384.0), 0.f, (float)(500.0/1113.0), (float)(125.0/192.0), (float)(-2187.0/6784.0), (float)(11.0/84.0)}
};
__constant__ float c_C[6] = {0.f, 0.2f, 0.3f, 0.8f, (float)(8.0/9.0), 1.f};

__device__ __forceinline__ float tanha(float x) {
  float r;
  asm("tanh.approx.f32 %0, %1;" : "=f"(r) : "f"(x));
  return r;
}
__device__ __forceinline__ __half2 tanha2(__half2 x) {
  unsigned ua = *reinterpret_cast<unsigned*>(&x), ur;
  asm("tanh.approx.f16x2 %0, %1;" : "=r"(ur) : "r"(ua));
  return *reinterpret_cast<__half2*>(&ur);
}
__device__ __forceinline__ __half2 u2h(unsigned x) { return *reinterpret_cast<__half2*>(&x); }

// ---------------- launch 1: combo = state init + augproj + u/v projection + deg zero ----------------
__global__ __launch_bounds__(256) void combo_kernel(
    const float* __restrict__ xh, const float* __restrict__ xm,
    const float* __restrict__ W1m, const float* __restrict__ b1m,
    const float* __restrict__ W1n, const float* __restrict__ b1n)
{
  __shared__ float saug[4][176];
  __shared__ float sW[32 * 64];
  __shared__ float sxi[4][16];
  __shared__ float sb[64];
  int b = blockIdx.x;
  int tid = threadIdx.x;
  int gid = b * 256 + tid;
  if (gid < NN) g_deg[gid] = 0;
  int ln = tid >> 6;
  int ch = tid & 63;
  int n = b * 4 + ln;
  #pragma unroll
  for (int i = tid; i < 512; i += 256) ((float4*)sW)[i] = ((const float4*)W1m)[i];
  if (tid < 16) ((float4*)sb)[tid] = ((const float4*)b1m)[tid];
  if (ch < 16) {
    int f = ch;
    float xs[10], ms[10];
    float sm = 0.f, cm = 0.f;
    #pragma unroll
    for (int tt = 0; tt < 10; tt++) {
      xs[tt] = xh[(tt * NN + n) * FF + f];
      ms[tt] = xm[tt * NN + n];
      sm += xs[tt] * ms[tt];
      cm += ms[tt];
    }
    float cnt = fmaxf(cm, 1.0f);
    float mean = sm / cnt;
    float var = 0.f;
    #pragma unroll
    for (int tt = 0; tt < 10; tt++) { float d = xs[tt] - mean; var += d * d * ms[tt]; }
    var /= cnt;
    #pragma unroll
    for (int tt = 0; tt < 9; tt++)
      saug[ln][tt * 16 + f] = (xs[tt + 1] - xs[tt]) * (ms[tt + 1] * ms[tt]);
    saug[ln][144 + f] = mean;
    saug[ln][160 + f] = var;
    int idx = n * 16 + f;
    float xv = xs[9];
    g_x0[idx] = xv;
    g_xi[idx] = xv;
    sxi[ln][f] = xv;
  }
  __syncthreads();
  {
    float acc = b1n[ch];
    #pragma unroll 8
    for (int r = 0; r < 176; r++)
      acc += saug[ln][r] * W1n[(32 + r) * 64 + ch];
    g_augproj[n * 64 + ch] = acc;
  }
  if (ch < 32) {
    int lane = ch;
    float u0 = 0.f, u1 = 0.f;
    float v0 = sb[lane], v1 = sb[32 + lane];
    #pragma unroll
    for (int i = 0; i < 16; i++) {
      float xv = sxi[ln][i];
      u0 += xv * sW[i * 64 + lane];
      u1 += xv * sW[i * 64 + 32 + lane];
      v0 += xv * sW[(16 + i) * 64 + lane];
      v1 += xv * sW[(16 + i) * 64 + 32 + lane];
    }
    g_uv[0][n * 32 + lane] = __floats2half2_rn(u0, u1);
    g_vv[n * 32 + lane]    = __floats2half2_rn(v0, v1);
  }
}

// ---------------- launch 2: single-block histogram + rowptr scan ----------------
__global__ __launch_bounds__(1024) void histscan_kernel(const int* __restrict__ ei) {
  __shared__ int wsum[32];
  int tid = threadIdx.x, lane = tid & 31, wid = tid >> 5;
  for (int e = tid; e < EE; e += 1024)
    atomicAdd(&g_deg[ei[EE + e]], 1);
  __syncthreads();
  int carry = 0;
  for (int base = 0; base < NN; base += 1024) {
    int i = base + tid;
    int v = (i < NN) ? g_deg[i] : 0;
    int x = v;
    #pragma unroll
    for (int o = 1; o < 32; o <<= 1) { int y = __shfl_up_sync(0xffffffffu, x, o); if (lane >= o) x += y; }
    if (lane == 31) wsum[wid] = x;
    __syncthreads();
    if (wid == 0) {
      int s = wsum[lane];
      #pragma unroll
      for (int o = 1; o < 32; o <<= 1) { int y = __shfl_up_sync(0xffffffffu, s, o); if (lane >= o) s += y; }
      wsum[lane] = s;
    }
    __syncthreads();
    int incl = x + carry + (wid > 0 ? wsum[wid - 1] : 0);
    if (i < NN) { g_rowptr[i + 1] = incl; g_wptr[i] = incl - v; }
    carry += wsum[31];
    __syncthreads();
  }
  if (tid == 0) g_rowptr[0] = 0;
}

// ---------------- launch 3: edge scatter into CSR (ea packed as 4 splat-half2) ----------------
__global__ __launch_bounds__(256) void scatter_kernel(
    const int* __restrict__ ei, const float* __restrict__ ea)
{
  int e = blockIdx.x * 256 + threadIdx.x;
  if (e < EE) {
    int d = ei[EE + e];
    int pos = atomicAdd(&g_wptr[d], 1);
    g_src_sorted[pos] = ei[e];
    float4 a = ((const float4*)ea)[e];
    __half2 hx = __floats2half2_rn(a.x, a.x);
    __half2 hy = __floats2half2_rn(a.y, a.y);
    __half2 hz = __floats2half2_rn(a.z, a.z);
    __half2 hw = __floats2half2_rn(a.w, a.w);
    uint4 q;
    q.x = *reinterpret_cast<unsigned*>(&hx);
    q.y = *reinterpret_cast<unsigned*>(&hy);
    q.z = *reinterpret_cast<unsigned*>(&hz);
    q.w = *reinterpret_cast<unsigned*>(&hw);
    g_ea2[pos] = q;
  }
}

// ---------------- launch 4..243: fused per-stage kernel, 2 nodes per warp ----------------
__global__ __launch_bounds__(256) void edge_node_kernel(
    int s, int it, int sub, int outrow, int pbuf,
    const float* __restrict__ t,
    const float* __restrict__ W1m, const float* __restrict__ W2m,
    const float* __restrict__ b2m, const float* __restrict__ W1n,
    const float* __restrict__ W2n, const float* __restrict__ b2n,
    const float* __restrict__ b1m)
{
  __shared__ float sWea[4 * 64];
  __shared__ float sW2m[64 * 16];
  __shared__ float sW1nx[16 * 64];
  __shared__ float sW1na[16 * 64];
  __shared__ float sW2n[64 * 16];
  __shared__ float sW1m[32 * 64];
  __shared__ float swt[64];
  __shared__ float sb1m[64];
  __shared__ float sb2m[16], sb2n[16];
  __shared__ float sbuf[8][128];   // 2 nodes x 64 ch per warp
  __shared__ float sxi[8][32];     // 2 nodes x 16
  __shared__ float sagg[8][32];
  __shared__ float sxin[8][32];

  int tid = threadIdx.x;
  if (tid < 64)  ((float4*)sWea)[tid] = ((const float4*)(W1m + 32 * 64))[tid];
  for (int i = tid; i < 256; i += 256) {
    ((float4*)sW2m)[i]  = ((const float4*)W2m)[i];
    ((float4*)sW1nx)[i] = ((const float4*)W1n)[i];
    ((float4*)sW1na)[i] = ((const float4*)(W1n + 1024))[i];
    ((float4*)sW2n)[i]  = ((const float4*)W2n)[i];
  }
  for (int i = tid; i < 512; i += 256) ((float4*)sW1m)[i] = ((const float4*)W1m)[i];
  if (tid < 16) ((float4*)swt)[tid]  = ((const float4*)(W1n + 208 * 64))[tid];
  if (tid >= 16 && tid < 32) ((float4*)sb1m)[tid - 16] = ((const float4*)b1m)[tid - 16];
  if (tid >= 32 && tid < 36) ((float4*)sb2m)[tid - 32] = ((const float4*)b2m)[tid - 32];
  if (tid >= 36 && tid < 40) ((float4*)sb2n)[tid - 36] = ((const float4*)b2n)[tid - 36];

  int w = tid >> 5, lane = tid & 31;
  int n0 = (blockIdx.x * 8 + w) * 2;   // warp owns nodes n0, n0+1 (contiguous)
  int n1 = n0 + 1;
  sxi[w][lane] = g_xi[n0 * 16 + lane];   // 32 floats = both nodes' xi, coalesced
  __syncthreads();

  float tA = t[it], tB = t[it + 1];
  float dti = (tB - tA) * 0.25f;
  float ti = tA + (float)sub * dti + c_C[s] * dti;

  const __half2* __restrict__ U = &g_uv[pbuf][0];
  // per-lane channel-pair edge weights in half2 (built from fp32 smem once)
  __half2 wxh = __floats2half2_rn(sWea[lane],       sWea[32 + lane]);
  __half2 wyh = __floats2half2_rn(sWea[64 + lane],  sWea[96 + lane]);
  __half2 wzh = __floats2half2_rn(sWea[128 + lane], sWea[160 + lane]);
  __half2 wwh = __floats2half2_rn(sWea[192 + lane], sWea[224 + lane]);
  __half2 vva = g_vv[n0 * 32 + lane];
  __half2 vvb = g_vv[n1 * 32 + lane];

  int bega = g_rowptr[n0];
  int begb = g_rowptr[n0 + 1];
  int endb = g_rowptr[n0 + 2];
  int da = begb - bega, db = endb - begb;

  float acc0a = 0.f, acc1a = 0.f, acc0b = 0.f, acc1b = 0.f;

  // ---- edge loop node0 (2-deep pipeline, half2 math) ----
  {
    int e = bega, end = begb;
    uint4 qc = make_uint4(0u,0u,0u,0u); __half2 uhc = __float2half2_rn(0.f);
    if (e < end) {
      int srcc = g_src_sorted[e];
      qc = g_ea2[e];
      uhc = U[srcc * 32 + lane];
    }
    for (; e < end; e++) {
      int e1 = e + 1;
      uint4 qn = qc; __half2 uhn = uhc;
      if (e1 < end) {
        int srcn = g_src_sorted[e1];
        qn = g_ea2[e1];
        uhn = U[srcn * 32 + lane];
      }
      __half2 a = __hadd2(uhc, vva);
      a = __hfma2(u2h(qc.x), wxh, a);
      a = __hfma2(u2h(qc.y), wyh, a);
      a = __hfma2(u2h(qc.z), wzh, a);
      a = __hfma2(u2h(qc.w), wwh, a);
      float2 tf = __half22float2(tanha2(a));
      acc0a += tf.x;
      acc1a += tf.y;
      qc = qn; uhc = uhn;
    }
  }
  // ---- edge loop node1 ----
  {
    int e = begb, end = endb;
    uint4 qc = make_uint4(0u,0u,0u,0u); __half2 uhc = __float2half2_rn(0.f);
    if (e < end) {
      int srcc = g_src_sorted[e];
      qc = g_ea2[e];
      uhc = U[srcc * 32 + lane];
    }
    for (; e < end; e++) {
      int e1 = e + 1;
      uint4 qn = qc; __half2 uhn = uhc;
      if (e1 < end) {
        int srcn = g_src_sorted[e1];
        qn = g_ea2[e1];
        uhn = U[srcn * 32 + lane];
      }
      __half2 a = __hadd2(uhc, vvb);
      a = __hfma2(u2h(qc.x), wxh, a);
      a = __hfma2(u2h(qc.y), wyh, a);
      a = __hfma2(u2h(qc.z), wzh, a);
      a = __hfma2(u2h(qc.w), wwh, a);
      float2 tf = __half22float2(tanha2(a));
      acc0b += tf.x;
      acc1b += tf.y;
      qc = qn; uhc = uhn;
    }
  }

  // ---- agg for both nodes: shared W2m reads, float4 h-vector broadcasts ----
  sbuf[w][lane]      = acc0a;
  sbuf[w][32 + lane] = acc1a;
  sbuf[w][64 + lane] = acc0b;
  sbuf[w][96 + lane] = acc1b;
  __syncwarp();
  int j = lane & 15;
  int cbase = (lane < 16) ? 0 : 32;
  float pa = 0.f, pb = 0.f;
  #pragma unroll
  for (int c4 = 0; c4 < 8; c4++) {
    float4 ha = ((const float4*)(sbuf[w] + cbase))[c4];
    float4 hb = ((const float4*)(sbuf[w] + 64 + cbase))[c4];
    float w0 = sW2m[(cbase + c4 * 4 + 0) * 16 + j];
    float w1 = sW2m[(cbase + c4 * 4 + 1) * 16 + j];
    float w2 = sW2m[(cbase + c4 * 4 + 2) * 16 + j];
    float w3 = sW2m[(cbase + c4 * 4 + 3) * 16 + j];
    pa += ha.x * w0 + ha.y * w1 + ha.z * w2 + ha.w * w3;
    pb += hb.x * w0 + hb.y * w1 + hb.z * w2 + hb.w * w3;
  }
  pa += __shfl_xor_sync(0xffffffffu, pa, 16);
  pb += __shfl_xor_sync(0xffffffffu, pb, 16);
  {
    int r = lane >> 4;
    float deg = (float)(r ? db : da);
    float pv = r ? pb : pa;
    sagg[w][lane] = pv + deg * sb2m[j];   // lane = r*16+j
  }
  __syncwarp();

  // ---- hidden layer for both nodes, shared weight reads ----
  float h0a = g_augproj[n0 * 64 + lane]      + ti * swt[lane];
  float h1a = g_augproj[n0 * 64 + 32 + lane] + ti * swt[32 + lane];
  float h0b = g_augproj[n1 * 64 + lane]      + ti * swt[lane];
  float h1b = g_augproj[n1 * 64 + 32 + lane] + ti * swt[32 + lane];
  #pragma unroll
  for (int i = 0; i < 16; i++) {
    float wxa = sW1nx[i * 64 + lane], wxb = sW1nx[i * 64 + 32 + lane];
    float waa = sW1na[i * 64 + lane], wab = sW1na[i * 64 + 32 + lane];
    float xva = sxi[w][i],  xvb = sxi[w][16 + i];
    float ava = sagg[w][i], avb = sagg[w][16 + i];
    h0a += xva * wxa + ava * waa;
    h1a += xva * wxb + ava * wab;
    h0b += xvb * wxa + avb * waa;
    h1b += xvb * wxb + avb * wab;
  }
  __syncwarp();
  sbuf[w][lane]      = tanha(h0a);
  sbuf[w][32 + lane] = tanha(h1a);
  sbuf[w][64 + lane] = tanha(h0b);
  sbuf[w][96 + lane] = tanha(h1b);
  __syncwarp();

  // ---- output layer for both nodes ----
  float oa = 0.f, ob = 0.f;
  #pragma unroll
  for (int c4 = 0; c4 < 8; c4++) {
    float4 ha = ((const float4*)(sbuf[w] + cbase))[c4];
    float4 hb = ((const float4*)(sbuf[w] + 64 + cbase))[c4];
    float w0 = sW2n[(cbase + c4 * 4 + 0) * 16 + j];
    float w1 = sW2n[(cbase + c4 * 4 + 1) * 16 + j];
    float w2 = sW2n[(cbase + c4 * 4 + 2) * 16 + j];
    float w3 = sW2n[(cbase + c4 * 4 + 3) * 16 + j];
    oa += ha.x * w0 + ha.y * w1 + ha.z * w2 + ha.w * w3;
    ob += hb.x * w0 + hb.y * w1 + hb.z * w2 + hb.w * w3;
  }
  oa += __shfl_xor_sync(0xffffffffu, oa, 16);
  ob += __shfl_xor_sync(0xffffffffu, ob, 16);

  // ---- epilogue: all 32 lanes active; lane = r*16 + j handles (node n0+r, col j) ----
  {
    int r = lane >> 4;
    int idx = (n0 + r) * 16 + j;            // lanes cover 32 contiguous floats
    float kval = (r ? ob : oa) + sb2n[j];
    g_k[s][idx] = kval;
    int row = (s < 5) ? s + 1 : 6;
    float acc = c_coef[row][s] * kval;
    #pragma unroll
    for (int jj = 0; jj < 5; jj++) {
      if (jj < s) acc += c_coef[row][jj] * g_k[jj][idx];
    }
    float xv = g_x0[idx] + dti * acc;
    if (s == 5) {
      g_x0[idx] = xv;
      if (outrow >= 0) g_ys[outrow * NF + idx] = xv;
    }
    g_xi[idx] = xv;
    sxin[w][lane] = xv;                      // lane = r*16+j
  }
  __syncwarp();

  // ---- u/v projection for both nodes, shared weight reads ----
  float u0a = 0.f, u1a = 0.f, u0b = 0.f, u1b = 0.f;
  float nv0a = sb1m[lane], nv1a = sb1m[32 + lane];
  float nv0b = nv0a, nv1b = nv1a;
  #pragma unroll
  for (int i = 0; i < 16; i++) {
    float wu0 = sW1m[i * 64 + lane],        wu1 = sW1m[i * 64 + 32 + lane];
    float wv0 = sW1m[(16 + i) * 64 + lane], wv1 = sW1m[(16 + i) * 64 + 32 + lane];
    float xa = sxin[w][i], xb = sxin[w][16 + i];
    u0a  += xa * wu0;  u1a  += xa * wu1;
    nv0a += xa * wv0;  nv1a += xa * wv1;
    u0b  += xb * wu0;  u1b  += xb * wu1;
    nv0b += xb * wv0;  nv1b += xb * wv1;
  }
  g_uv[pbuf ^ 1][n0 * 32 + lane] = __floats2half2_rn(u0a, u1a);
  g_uv[pbuf ^ 1][n1 * 32 + lane] = __floats2half2_rn(u0b, u1b);
  g_vv[n0 * 32 + lane] = __floats2half2_rn(nv0a, nv1a);
  g_vv[n1 * 32 + lane] = __floats2half2_rn(nv0b, nv1b);
}

__global__ __launch_bounds__(256) void gather_out_kernel(
    const int* __restrict__ mask_idx, float* __restrict__ out)
{
  int idx = blockIdx.x * 256 + threadIdx.x;
  if (idx < TOUT * NF) {
    int row = idx / NF;
    int rem = idx - row * NF;
    out[idx] = g_ys[mask_idx[row] * NF + rem];
  }
}

// ---------------- launcher ----------------
extern "C" void kernel_launch(void* const* d_in, const int* in_sizes, int n_in,
                              void* d_out, int out_size)
{
  const float* x_hist   = (const float*)d_in[0];
  const float* x_mask   = (const float*)d_in[1];
  const int*   ei       = (const int*)d_in[2];
  const float* ea       = (const float*)d_in[3];
  const float* t        = (const float*)d_in[4];
  const int*   mask_idx = (const int*)d_in[5];
  const float* W1m = (const float*)d_in[6];
  const float* b1m = (const float*)d_in[7];
  const float* W2m = (const float*)d_in[8];
  const float* b2m = (const float*)d_in[9];
  const float* W1n = (const float*)d_in[10];
  const float* b1n = (const float*)d_in[11];
  const float* W2n = (const float*)d_in[12];
  const float* b2n = (const float*)d_in[13];
  float* out = (float*)d_out;

  // exactly 3 setup launches -> the 4th process launch is edge_node_kernel (ncu target)
  combo_kernel<<<NN / 4, 256>>>(x_hist, x_mask, W1m, b1m, W1n, b1n);   // 1
  histscan_kernel<<<1, 1024>>>(ei);                                     // 2
  scatter_kernel<<<(EE + 255) / 256, 256>>>(ei, ea);                    // 3

  int L = 0;
  for (int it = 0; it < TOUT; it++) {
    for (int sub = 0; sub < 4; sub++) {
      for (int s = 0; s < 6; s++) {
        int outrow = (s == 5 && sub == 3) ? it : -1;
        edge_node_kernel<<<NN / 16, 256>>>(s, it, sub, outrow, L & 1,
                                           t, W1m, W2m, b2m, W1n, W2n, b2n, b1m);
        L++;
      }
    }
  }

  gather_out_kernel<<<(TOUT * NF + 255) / 256, 256>>>(mask_idx, out);
}

// round 17
// speedup vs baseline: 1.0554x; 1.0022x over previous
#include <cuda_runtime.h>
#include <cuda_fp16.h>

#define NN 50000
#define FF 16
#define EE 800000
#define HH 64
#define TOUT 10
#define NF (NN*FF)

// ---------------- device state ----------------
__device__ float   g_x0[NF];
__device__ float   g_xi[NF];
__device__ float   g_k[6][NF];
__device__ __half2 g_uv[2][NN*32];   // packed u: (.x=ch lane, .y=ch lane+32), double-buffered
__device__ __half2 g_vv[NN*32];      // packed v
__device__ float   g_augproj[NN*HH];
__device__ float   g_ys[TOUT*NF];
__device__ int     g_deg[NN];
__device__ int     g_rowptr[NN+1];
__device__ int     g_wptr[NN];
__device__ int     g_src_sorted[EE];
__device__ uint4   g_ea2[EE];        // ea pre-packed: 4 splat-half2 per edge

// DOPRI5 coefficients. Row 0 unused, rows 1..5 = A[0..4], row 6 = B.
__constant__ float c_coef[7][6] = {
  {0.f,0.f,0.f,0.f,0.f,0.f},
  {(float)(0.2), 0.f,0.f,0.f,0.f,0.f},
  {(float)(3.0/40.0), (float)(9.0/40.0), 0.f,0.f,0.f,0.f},
  {(float)(44.0/45.0), (float)(-56.0/15.0), (float)(32.0/9.0), 0.f,0.f,0.f},
  {(float)(19372.0/6561.0), (float)(-25360.0/2187.0), (float)(64448.0/6561.0), (float)(-212.0/729.0), 0.f,0.f},
  {(float)(9017.0/3168.0), (float)(-355.0/33.0), (float)(46732.0/5247.0), (float)(49.0/176.0), (float)(-5103.0/18656.0), 0.f},
  {(float)(35.0/384.0), 0.f, (float)(500.0/1113.0), (float)(125.0/192.0), (float)(-2187.0/6784.0), (float)(11.0/84.0)}
};
__constant__ float c_C[6] = {0.f, 0.2f, 0.3f, 0.8f, (float)(8.0/9.0), 1.f};

__device__ __forceinline__ float tanha(float x) {
  float r;
  asm("tanh.approx.f32 %0, %1;" : "=f"(r) : "f"(x));
  return r;
}
__device__ __forceinline__ __half2 tanha2(__half2 x) {
  unsigned ua = *reinterpret_cast<unsigned*>(&x), ur;
  asm("tanh.approx.f16x2 %0, %1;" : "=r"(ur) : "r"(ua));
  return *reinterpret_cast<__half2*>(&ur);
}
__device__ __forceinline__ __half2 u2h(unsigned x) { return *reinterpret_cast<__half2*>(&x); }

// ---------------- launch 1: combo = state init + augproj + u/v projection + deg zero ----------------
__global__ __launch_bounds__(256) void combo_kernel(
    const float* __restrict__ xh, const float* __restrict__ xm,
    const float* __restrict__ W1m, const float* __restrict__ b1m,
    const float* __restrict__ W1n, const float* __restrict__ b1n)
{
  __shared__ float saug[4][176];
  __shared__ float sW[32 * 64];
  __shared__ float sxi[4][16];
  __shared__ float sb[64];
  int b = blockIdx.x;
  int tid = threadIdx.x;
  int gid = b * 256 + tid;
  if (gid < NN) g_deg[gid] = 0;
  int ln = tid >> 6;
  int ch = tid & 63;
  int n = b * 4 + ln;
  #pragma unroll
  for (int i = tid; i < 512; i += 256) ((float4*)sW)[i] = ((const float4*)W1m)[i];
  if (tid < 16) ((float4*)sb)[tid] = ((const float4*)b1m)[tid];
  if (ch < 16) {
    int f = ch;
    float xs[10], ms[10];
    float sm = 0.f, cm = 0.f;
    #pragma unroll
    for (int tt = 0; tt < 10; tt++) {
      xs[tt] = xh[(tt * NN + n) * FF + f];
      ms[tt] = xm[tt * NN + n];
      sm += xs[tt] * ms[tt];
      cm += ms[tt];
    }
    float cnt = fmaxf(cm, 1.0f);
    float mean = sm / cnt;
    float var = 0.f;
    #pragma unroll
    for (int tt = 0; tt < 10; tt++) { float d = xs[tt] - mean; var += d * d * ms[tt]; }
    var /= cnt;
    #pragma unroll
    for (int tt = 0; tt < 9; tt++)
      saug[ln][tt * 16 + f] = (xs[tt + 1] - xs[tt]) * (ms[tt + 1] * ms[tt]);
    saug[ln][144 + f] = mean;
    saug[ln][160 + f] = var;
    int idx = n * 16 + f;
    float xv = xs[9];
    g_x0[idx] = xv;
    g_xi[idx] = xv;
    sxi[ln][f] = xv;
  }
  __syncthreads();
  {
    float acc = b1n[ch];
    #pragma unroll 8
    for (int r = 0; r < 176; r++)
      acc += saug[ln][r] * W1n[(32 + r) * 64 + ch];
    g_augproj[n * 64 + ch] = acc;
  }
  if (ch < 32) {
    int lane = ch;
    float u0 = 0.f, u1 = 0.f;
    float v0 = sb[lane], v1 = sb[32 + lane];
    #pragma unroll
    for (int i = 0; i < 16; i++) {
      float xv = sxi[ln][i];
      u0 += xv * sW[i * 64 + lane];
      u1 += xv * sW[i * 64 + 32 + lane];
      v0 += xv * sW[(16 + i) * 64 + lane];
      v1 += xv * sW[(16 + i) * 64 + 32 + lane];
    }
    g_uv[0][n * 32 + lane] = __floats2half2_rn(u0, u1);
    g_vv[n * 32 + lane]    = __floats2half2_rn(v0, v1);
  }
}

// ---------------- launch 2: single-block histogram + rowptr scan ----------------
__global__ __launch_bounds__(1024) void histscan_kernel(const int* __restrict__ ei) {
  __shared__ int wsum[32];
  int tid = threadIdx.x, lane = tid & 31, wid = tid >> 5;
  for (int e = tid; e < EE; e += 1024)
    atomicAdd(&g_deg[ei[EE + e]], 1);
  __syncthreads();
  int carry = 0;
  for (int base = 0; base < NN; base += 1024) {
    int i = base + tid;
    int v = (i < NN) ? g_deg[i] : 0;
    int x = v;
    #pragma unroll
    for (int o = 1; o < 32; o <<= 1) { int y = __shfl_up_sync(0xffffffffu, x, o); if (lane >= o) x += y; }
    if (lane == 31) wsum[wid] = x;
    __syncthreads();
    if (wid == 0) {
      int s = wsum[lane];
      #pragma unroll
      for (int o = 1; o < 32; o <<= 1) { int y = __shfl_up_sync(0xffffffffu, s, o); if (lane >= o) s += y; }
      wsum[lane] = s;
    }
    __syncthreads();
    int incl = x + carry + (wid > 0 ? wsum[wid - 1] : 0);
    if (i < NN) { g_rowptr[i + 1] = incl; g_wptr[i] = incl - v; }
    carry += wsum[31];
    __syncthreads();
  }
  if (tid == 0) g_rowptr[0] = 0;
}

// ---------------- launch 3: edge scatter into CSR (ea packed as 4 splat-half2) ----------------
__global__ __launch_bounds__(256) void scatter_kernel(
    const int* __restrict__ ei, const float* __restrict__ ea)
{
  int e = blockIdx.x * 256 + threadIdx.x;
  if (e < EE) {
    int d = ei[EE + e];
    int pos = atomicAdd(&g_wptr[d], 1);
    g_src_sorted[pos] = ei[e];
    float4 a = ((const float4*)ea)[e];
    __half2 hx = __floats2half2_rn(a.x, a.x);
    __half2 hy = __floats2half2_rn(a.y, a.y);
    __half2 hz = __floats2half2_rn(a.z, a.z);
    __half2 hw = __floats2half2_rn(a.w, a.w);
    uint4 q;
    q.x = *reinterpret_cast<unsigned*>(&hx);
    q.y = *reinterpret_cast<unsigned*>(&hy);
    q.z = *reinterpret_cast<unsigned*>(&hz);
    q.w = *reinterpret_cast<unsigned*>(&hw);
    g_ea2[pos] = q;
  }
}

// ---------------- launch 4..243: fused per-stage kernel, 2 nodes per warp ----------------
__global__ __launch_bounds__(256, 5) void edge_node_kernel(
    int s, int it, int sub, int outrow, int pbuf,
    const float* __restrict__ t,
    const float* __restrict__ W1m, const float* __restrict__ W2m,
    const float* __restrict__ b2m, const float* __restrict__ W1n,
    const float* __restrict__ W2n, const float* __restrict__ b2n,
    const float* __restrict__ b1m)
{
  __shared__ float  sWea[4 * 64];
  __shared__ float  sW2m[64 * 16];
  __shared__ float2 sW1nxP[16 * 32];   // [(i,lane)] = (W1n[i][lane], W1n[i][lane+32])
  __shared__ float2 sW1naP[16 * 32];
  __shared__ float  sW2n[64 * 16];
  __shared__ float2 sW1mUP[16 * 32];   // W1m rows 0..15 (u projection)
  __shared__ float2 sW1mVP[16 * 32];   // W1m rows 16..31 (v projection)
  __shared__ float  swt[64];
  __shared__ float  sb1m[64];
  __shared__ float  sb2m[16], sb2n[16];
  __shared__ float  sbuf[8][128];   // 2 nodes x 64 ch per warp
  __shared__ float  sxi[8][32];     // 2 nodes x 16
  __shared__ float  sagg[8][32];
  __shared__ float  sxin[8][32];

  int tid = threadIdx.x;
  if (tid < 64)  ((float4*)sWea)[tid] = ((const float4*)(W1m + 32 * 64))[tid];
  for (int i = tid; i < 256; i += 256) {
    ((float4*)sW2m)[i]  = ((const float4*)W2m)[i];
    ((float4*)sW2n)[i]  = ((const float4*)W2n)[i];
  }
  for (int i = tid; i < 512; i += 256) {
    int r = i >> 5, l = i & 31;
    sW1nxP[i] = make_float2(W1n[r * 64 + l],         W1n[r * 64 + 32 + l]);
    sW1naP[i] = make_float2(W1n[1024 + r * 64 + l],  W1n[1024 + r * 64 + 32 + l]);
    sW1mUP[i] = make_float2(W1m[r * 64 + l],         W1m[r * 64 + 32 + l]);
    sW1mVP[i] = make_float2(W1m[(16 + r) * 64 + l],  W1m[(16 + r) * 64 + 32 + l]);
  }
  if (tid < 16) ((float4*)swt)[tid]  = ((const float4*)(W1n + 208 * 64))[tid];
  if (tid >= 16 && tid < 32) ((float4*)sb1m)[tid - 16] = ((const float4*)b1m)[tid - 16];
  if (tid >= 32 && tid < 36) ((float4*)sb2m)[tid - 32] = ((const float4*)b2m)[tid - 32];
  if (tid >= 36 && tid < 40) ((float4*)sb2n)[tid - 36] = ((const float4*)b2n)[tid - 36];

  int w = tid >> 5, lane = tid & 31;
  int n0 = (blockIdx.x * 8 + w) * 2;   // warp owns nodes n0, n0+1 (contiguous)
  int n1 = n0 + 1;
  sxi[w][lane] = g_xi[n0 * 16 + lane];   // 32 floats = both nodes' xi, coalesced
  __syncthreads();

  float tA = t[it], tB = t[it + 1];
  float dti = (tB - tA) * 0.25f;
  float ti = tA + (float)sub * dti + c_C[s] * dti;

  const __half2* __restrict__ U = &g_uv[pbuf][0];
  // per-lane channel-pair edge weights in half2 (built from fp32 smem once)
  __half2 wxh = __floats2half2_rn(sWea[lane],       sWea[32 + lane]);
  __half2 wyh = __floats2half2_rn(sWea[64 + lane],  sWea[96 + lane]);
  __half2 wzh = __floats2half2_rn(sWea[128 + lane], sWea[160 + lane]);
  __half2 wwh = __floats2half2_rn(sWea[192 + lane], sWea[224 + lane]);
  __half2 vva = g_vv[n0 * 32 + lane];
  __half2 vvb = g_vv[n1 * 32 + lane];

  int bega = g_rowptr[n0];
  int begb = g_rowptr[n0 + 1];
  int endb = g_rowptr[n0 + 2];
  int da = begb - bega, db = endb - begb;

  float acc0a = 0.f, acc1a = 0.f, acc0b = 0.f, acc1b = 0.f;

  // ---- edge loop node0 (2-deep pipeline, half2 math, R16-proven) ----
  {
    int e = bega, end = begb;
    uint4 qc = make_uint4(0u,0u,0u,0u); __half2 uhc = __float2half2_rn(0.f);
    if (e < end) {
      int srcc = g_src_sorted[e];
      qc = g_ea2[e];
      uhc = U[srcc * 32 + lane];
    }
    for (; e < end; e++) {
      int e1 = e + 1;
      uint4 qn = qc; __half2 uhn = uhc;
      if (e1 < end) {
        int srcn = g_src_sorted[e1];
        qn = g_ea2[e1];
        uhn = U[srcn * 32 + lane];
      }
      __half2 a = __hadd2(uhc, vva);
      a = __hfma2(u2h(qc.x), wxh, a);
      a = __hfma2(u2h(qc.y), wyh, a);
      a = __hfma2(u2h(qc.z), wzh, a);
      a = __hfma2(u2h(qc.w), wwh, a);
      float2 tf = __half22float2(tanha2(a));
      acc0a += tf.x;
      acc1a += tf.y;
      qc = qn; uhc = uhn;
    }
  }
  // ---- edge loop node1 ----
  {
    int e = begb, end = endb;
    uint4 qc = make_uint4(0u,0u,0u,0u); __half2 uhc = __float2half2_rn(0.f);
    if (e < end) {
      int srcc = g_src_sorted[e];
      qc = g_ea2[e];
      uhc = U[srcc * 32 + lane];
    }
    for (; e < end; e++) {
      int e1 = e + 1;
      uint4 qn = qc; __half2 uhn = uhc;
      if (e1 < end) {
        int srcn = g_src_sorted[e1];
        qn = g_ea2[e1];
        uhn = U[srcn * 32 + lane];
      }
      __half2 a = __hadd2(uhc, vvb);
      a = __hfma2(u2h(qc.x), wxh, a);
      a = __hfma2(u2h(qc.y), wyh, a);
      a = __hfma2(u2h(qc.z), wzh, a);
      a = __hfma2(u2h(qc.w), wwh, a);
      float2 tf = __half22float2(tanha2(a));
      acc0b += tf.x;
      acc1b += tf.y;
      qc = qn; uhc = uhn;
    }
  }

  // ---- agg for both nodes: shared W2m reads, float4 h-vector broadcasts ----
  sbuf[w][lane]      = acc0a;
  sbuf[w][32 + lane] = acc1a;
  sbuf[w][64 + lane] = acc0b;
  sbuf[w][96 + lane] = acc1b;
  __syncwarp();
  int j = lane & 15;
  int cbase = (lane < 16) ? 0 : 32;
  float pa = 0.f, pb = 0.f;
  #pragma unroll
  for (int c4 = 0; c4 < 8; c4++) {
    float4 ha = ((const float4*)(sbuf[w] + cbase))[c4];
    float4 hb = ((const float4*)(sbuf[w] + 64 + cbase))[c4];
    float w0 = sW2m[(cbase + c4 * 4 + 0) * 16 + j];
    float w1 = sW2m[(cbase + c4 * 4 + 1) * 16 + j];
    float w2 = sW2m[(cbase + c4 * 4 + 2) * 16 + j];
    float w3 = sW2m[(cbase + c4 * 4 + 3) * 16 + j];
    pa += ha.x * w0 + ha.y * w1 + ha.z * w2 + ha.w * w3;
    pb += hb.x * w0 + hb.y * w1 + hb.z * w2 + hb.w * w3;
  }
  pa += __shfl_xor_sync(0xffffffffu, pa, 16);
  pb += __shfl_xor_sync(0xffffffffu, pb, 16);
  {
    int r = lane >> 4;
    float deg = (float)(r ? db : da);
    float pv = r ? pb : pa;
    sagg[w][lane] = pv + deg * sb2m[j];   // lane = r*16+j
  }
  __syncwarp();

  // ---- hidden layer for both nodes: float2-packed weights + float4 data reads ----
  float h0a = g_augproj[n0 * 64 + lane]      + ti * swt[lane];
  float h1a = g_augproj[n0 * 64 + 32 + lane] + ti * swt[32 + lane];
  float h0b = g_augproj[n1 * 64 + lane]      + ti * swt[lane];
  float h1b = g_augproj[n1 * 64 + 32 + lane] + ti * swt[32 + lane];
  #pragma unroll
  for (int i4 = 0; i4 < 4; i4++) {
    float4 Xa = ((const float4*)(sxi[w]))[i4];
    float4 Xb = ((const float4*)(sxi[w] + 16))[i4];
    float4 Aa = ((const float4*)(sagg[w]))[i4];
    float4 Ab = ((const float4*)(sagg[w] + 16))[i4];
    #pragma unroll
    for (int k = 0; k < 4; k++) {
      int i = i4 * 4 + k;
      float2 wx = sW1nxP[i * 32 + lane];
      float2 wa = sW1naP[i * 32 + lane];
      float xa = ((const float*)&Xa)[k], xb = ((const float*)&Xb)[k];
      float aa = ((const float*)&Aa)[k], ab = ((const float*)&Ab)[k];
      h0a += xa * wx.x + aa * wa.x;
      h1a += xa * wx.y + aa * wa.y;
      h0b += xb * wx.x + ab * wa.x;
      h1b += xb * wx.y + ab * wa.y;
    }
  }
  __syncwarp();
  sbuf[w][lane]      = tanha(h0a);
  sbuf[w][32 + lane] = tanha(h1a);
  sbuf[w][64 + lane] = tanha(h0b);
  sbuf[w][96 + lane] = tanha(h1b);
  __syncwarp();

  // ---- output layer for both nodes ----
  float oa = 0.f, ob = 0.f;
  #pragma unroll
  for (int c4 = 0; c4 < 8; c4++) {
    float4 ha = ((const float4*)(sbuf[w] + cbase))[c4];
    float4 hb = ((const float4*)(sbuf[w] + 64 + cbase))[c4];
    float w0 = sW2n[(cbase + c4 * 4 + 0) * 16 + j];
    float w1 = sW2n[(cbase + c4 * 4 + 1) * 16 + j];
    float w2 = sW2n[(cbase + c4 * 4 + 2) * 16 + j];
    float w3 = sW2n[(cbase + c4 * 4 + 3) * 16 + j];
    oa += ha.x * w0 + ha.y * w1 + ha.z * w2 + ha.w * w3;
    ob += hb.x * w0 + hb.y * w1 + hb.z * w2 + hb.w * w3;
  }
  oa += __shfl_xor_sync(0xffffffffu, oa, 16);
  ob += __shfl_xor_sync(0xffffffffu, ob, 16);

  // ---- epilogue: all 32 lanes active; lane = r*16 + j handles (node n0+r, col j) ----
  {
    int r = lane >> 4;
    int idx = (n0 + r) * 16 + j;            // lanes cover 32 contiguous floats
    float kval = (r ? ob : oa) + sb2n[j];
    g_k[s][idx] = kval;
    int row = (s < 5) ? s + 1 : 6;
    float acc = c_coef[row][s] * kval;
    #pragma unroll
    for (int jj = 0; jj < 5; jj++) {
      if (jj < s) acc += c_coef[row][jj] * g_k[jj][idx];
    }
    float xv = g_x0[idx] + dti * acc;
    if (s == 5) {
      g_x0[idx] = xv;
      if (outrow >= 0) g_ys[outrow * NF + idx] = xv;
    }
    g_xi[idx] = xv;
    sxin[w][lane] = xv;                      // lane = r*16+j
  }
  __syncwarp();

  // ---- u/v projection for both nodes: float2-packed weights + float4 data reads ----
  float u0a = 0.f, u1a = 0.f, u0b = 0.f, u1b = 0.f;
  float nv0a = sb1m[lane], nv1a = sb1m[32 + lane];
  float nv0b = nv0a, nv1b = nv1a;
  #pragma unroll
  for (int i4 = 0; i4 < 4; i4++) {
    float4 Xa = ((const float4*)(sxin[w]))[i4];
    float4 Xb = ((const float4*)(sxin[w] + 16))[i4];
    #pragma unroll
    for (int k = 0; k < 4; k++) {
      int i = i4 * 4 + k;
      float2 wu = sW1mUP[i * 32 + lane];
      float2 wv = sW1mVP[i * 32 + lane];
      float xa = ((const float*)&Xa)[k], xb = ((const float*)&Xb)[k];
      u0a  += xa * wu.x;  u1a  += xa * wu.y;
      nv0a += xa * wv.x;  nv1a += xa * wv.y;
      u0b  += xb * wu.x;  u1b  += xb * wu.y;
      nv0b += xb * wv.x;  nv1b += xb * wv.y;
    }
  }
  g_uv[pbuf ^ 1][n0 * 32 + lane] = __floats2half2_rn(u0a, u1a);
  g_uv[pbuf ^ 1][n1 * 32 + lane] = __floats2half2_rn(u0b, u1b);
  g_vv[n0 * 32 + lane] = __floats2half2_rn(nv0a, nv1a);
  g_vv[n1 * 32 + lane] = __floats2half2_rn(nv0b, nv1b);
}

__global__ __launch_bounds__(256) void gather_out_kernel(
    const int* __restrict__ mask_idx, float* __restrict__ out)
{
  int idx = blockIdx.x * 256 + threadIdx.x;
  if (idx < TOUT * NF) {
    int row = idx / NF;
    int rem = idx - row * NF;
    out[idx] = g_ys[mask_idx[row] * NF + rem];
  }
}

// ---------------- launcher ----------------
extern "C" void kernel_launch(void* const* d_in, const int* in_sizes, int n_in,
                              void* d_out, int out_size)
{
  const float* x_hist   = (const float*)d_in[0];
  const float* x_mask   = (const float*)d_in[1];
  const int*   ei       = (const int*)d_in[2];
  const float* ea       = (const float*)d_in[3];
  const float* t        = (const float*)d_in[4];
  const int*   mask_idx = (const int*)d_in[5];
  const float* W1m = (const float*)d_in[6];
  const float* b1m = (const float*)d_in[7];
  const float* W2m = (const float*)d_in[8];
  const float* b2m = (const float*)d_in[9];
  const float* W1n = (const float*)d_in[10];
  const float* b1n = (const float*)d_in[11];
  const float* W2n = (const float*)d_in[12];
  const float* b2n = (const float*)d_in[13];
  float* out = (float*)d_out;

  // exactly 3 setup launches -> the 4th process launch is edge_node_kernel (ncu target)
  combo_kernel<<<NN / 4, 256>>>(x_hist, x_mask, W1m, b1m, W1n, b1n);   // 1
  histscan_kernel<<<1, 1024>>>(ei);                                     // 2
  scatter_kernel<<<(EE + 255) / 256, 256>>>(ei, ea);                    // 3

  int L = 0;
  for (int it = 0; it < TOUT; it++) {
    for (int sub = 0; sub < 4; sub++) {
      for (int s = 0; s < 6; s++) {
        int outrow = (s == 5 && sub == 3) ? it : -1;
        edge_node_kernel<<<NN / 16, 256>>>(s, it, sub, outrow, L & 1,
                                           t, W1m, W2m, b2m, W1n, W2n, b2n, b1m);
        L++;
      }
    }
  }

  gather_out_kernel<<<(TOUT * NF + 255) / 256, 256>>>(mask_idx, out);
}